// round 13
// baseline (speedup 1.0000x reference)
#include <cuda_runtime.h>
#include <cstdint>

#define BS   256
#define SEQ  512
#define H    768

// Scratch (no allocations allowed)
__device__ float g_emb[BS * H];           // gathered "embraced" rows
__device__ float g_S[2 * BS * H];         // S0 = cls@Wtop, S1 = cls@Wbot
__device__ float g_S2[2][BS * H];         // emb@Wbot, K-split halves

// ---------------------------------------------------------------------------
// Threefry-2x32, 20 rounds, key = (0, 42), partitionable scheme:
//   bits32(i) = x0 ^ x1 of threefry2x32(key, (0, i))
// ---------------------------------------------------------------------------
__device__ __forceinline__ uint32_t rotl32(uint32_t x, int r) {
    return (x << r) | (x >> (32 - r));
}

__device__ __forceinline__ uint32_t threefry_bits_partitionable(uint32_t i) {
    const uint32_t k0 = 0u, k1 = 42u;
    const uint32_t ks2 = 0x1BD11BDAu ^ k0 ^ k1;
    uint32_t x0 = 0u + k0;
    uint32_t x1 = i  + k1;

#define TF_BLOCK(r0_, r1_, r2_, r3_)                                   \
    x0 += x1; x1 = rotl32(x1, r0_); x1 ^= x0;                          \
    x0 += x1; x1 = rotl32(x1, r1_); x1 ^= x0;                          \
    x0 += x1; x1 = rotl32(x1, r2_); x1 ^= x0;                          \
    x0 += x1; x1 = rotl32(x1, r3_); x1 ^= x0;

    TF_BLOCK(13, 15, 26, 6)   x0 += k1;  x1 += ks2 + 1u;
    TF_BLOCK(17, 29, 16, 24)  x0 += ks2; x1 += k0  + 2u;
    TF_BLOCK(13, 15, 26, 6)   x0 += k0;  x1 += k1  + 3u;
    TF_BLOCK(17, 29, 16, 24)  x0 += k1;  x1 += ks2 + 4u;
    TF_BLOCK(13, 15, 26, 6)   x0 += ks2; x1 += k0  + 5u;
#undef TF_BLOCK
    return x0 ^ x1;
}

// fast tanh via MUFU.EX2: exact limits at +-inf
__device__ __forceinline__ float fast_tanh(float x) {
    return 1.0f - 2.0f / (__expf(2.0f * x) + 1.0f);
}

// ---------------------------------------------------------------------------
// GEMM machinery (TF32 mma + cp.async). Raw f32 bits -> mma.tf32 truncation.
// BM=64, BN=64, BK=16, NSTAGE=4 (R8-proven config).
// ---------------------------------------------------------------------------
#define BK     16
#define NSTAGE 4
#define APAD   20
#define BPAD   72
#define A_WORDS (64 * APAD)   // 1280
#define B_WORDS (BK * BPAD)   // 1152

__device__ __forceinline__ void cp16(uint32_t saddr, const void* gaddr) {
    asm volatile("cp.async.ca.shared.global [%0], [%1], 16;\n"
                 :: "r"(saddr), "l"(gaddr));
}
__device__ __forceinline__ void cp_commit() {
    asm volatile("cp.async.commit_group;\n");
}
template <int N>
__device__ __forceinline__ void cp_wait() {
    asm volatile("cp.async.wait_group %0;\n" :: "n"(N));
}
__device__ __forceinline__ void bar_gemm() {     // barrier for the 256 GEMM threads only
    asm volatile("bar.sync 0, 256;" ::: "memory");
}

__device__ __forceinline__ void mma_tf32(float* d, const uint32_t* a, const uint32_t* b) {
    asm volatile(
        "mma.sync.aligned.m16n8k8.row.col.f32.tf32.tf32.f32 "
        "{%0,%1,%2,%3}, {%4,%5,%6,%7}, {%8,%9}, {%0,%1,%2,%3};\n"
        : "+f"(d[0]), "+f"(d[1]), "+f"(d[2]), "+f"(d[3])
        : "r"(a[0]), "r"(a[1]), "r"(a[2]), "r"(a[3]), "r"(b[0]), "r"(b[1]));
}

// Core GEMM: C[m0..+64, n0..+64] (+)= A[m0.., kb..ke] * B[kb..ke, n0..]
// Runs on 256 threads (warps 0-7). Barrier: bar.sync 0,256.
template <bool USE_NAMED_BAR>
__device__ __forceinline__ void gemm_tile(const float* __restrict__ A,
                                          const float* __restrict__ Bsrc,
                                          float* __restrict__ Cp,
                                          int m0, int n0, int kb, int nit,
                                          uint32_t* As_base, uint32_t* Bs_base,
                                          int tid) {
    const int warp = tid >> 5;
    const int lane = tid & 31;
    const int wm   = (warp & 1) * 32;
    const int wn   = (warp >> 1) * 16;
    const int grp  = lane >> 2;
    const int tig  = lane & 3;

    const int a_r = tid >> 2;
    const int a_c = (tid & 3) * 4;
    const int b_r = tid >> 4;
    const int b_c = (tid & 15) * 4;

    const float* a_src = &A[(m0 + a_r) * H + kb + a_c];
    const float* b_src = &Bsrc[(size_t)(kb + b_r) * H + n0 + b_c];

    const uint32_t s_as = (uint32_t)__cvta_generic_to_shared(As_base) +
                          (uint32_t)((a_r * APAD + a_c) * 4);
    const uint32_t s_bs = (uint32_t)__cvta_generic_to_shared(Bs_base) +
                          (uint32_t)((b_r * BPAD + b_c) * 4);

    float acc[2][2][4];
#pragma unroll
    for (int mi = 0; mi < 2; mi++)
#pragma unroll
        for (int ni = 0; ni < 2; ni++)
#pragma unroll
            for (int r = 0; r < 4; r++) acc[mi][ni][r] = 0.0f;

#pragma unroll
    for (int s = 0; s < NSTAGE - 1; s++) {
        cp16(s_as + (uint32_t)(s * A_WORDS * 4), a_src + s * BK);
        cp16(s_bs + (uint32_t)(s * B_WORDS * 4), b_src + (size_t)(s * BK) * H);
        cp_commit();
    }

    for (int it = 0; it < nit; it++) {
        cp_wait<NSTAGE - 2>();
        if (USE_NAMED_BAR) bar_gemm(); else __syncthreads();

        const int nx = it + NSTAGE - 1;
        if (nx < nit) {
            const int buf = nx & (NSTAGE - 1);
            cp16(s_as + (uint32_t)(buf * A_WORDS * 4), a_src + nx * BK);
            cp16(s_bs + (uint32_t)(buf * B_WORDS * 4), b_src + (size_t)(nx * BK) * H);
        }
        cp_commit();

        const uint32_t* Asb = As_base + (it & (NSTAGE - 1)) * A_WORDS;
        const uint32_t* Bsb = Bs_base + (it & (NSTAGE - 1)) * B_WORDS;
#pragma unroll
        for (int ks = 0; ks < BK; ks += 8) {
            uint32_t afr[2][4];
#pragma unroll
            for (int mi = 0; mi < 2; mi++) {
                const int rbase = (wm + mi * 16 + grp) * APAD + ks + tig;
                afr[mi][0] = Asb[rbase];
                afr[mi][1] = Asb[rbase + 8 * APAD];
                afr[mi][2] = Asb[rbase + 4];
                afr[mi][3] = Asb[rbase + 8 * APAD + 4];
            }
            uint32_t bfr[2][2];
#pragma unroll
            for (int ni = 0; ni < 2; ni++) {
                const int cbase = (ks + tig) * BPAD + wn + ni * 8 + grp;
                bfr[ni][0] = Bsb[cbase];
                bfr[ni][1] = Bsb[cbase + 4 * BPAD];
            }
#pragma unroll
            for (int mi = 0; mi < 2; mi++)
#pragma unroll
                for (int ni = 0; ni < 2; ni++)
                    mma_tf32(acc[mi][ni], afr[mi], bfr[ni]);
        }
    }

#pragma unroll
    for (int mi = 0; mi < 2; mi++) {
#pragma unroll
        for (int ni = 0; ni < 2; ni++) {
            const int col = n0 + wn + ni * 8 + tig * 2;
            const int r0  = m0 + wm + mi * 16 + grp;
            *reinterpret_cast<float2*>(&Cp[(size_t)r0 * H + col]) =
                make_float2(acc[mi][ni][0], acc[mi][ni][1]);
            *reinterpret_cast<float2*>(&Cp[(size_t)(r0 + 8) * H + col]) =
                make_float2(acc[mi][ni][2], acc[mi][ni][3]);
        }
    }
}

// ---------------------------------------------------------------------------
// Kernel 1 (fused): 144 blocks x 384 threads.
//   warps 0-7  : cls GEMM, groups 0/1 (96 tiles; blocks 96..143 idle here)
//   warps 8-11 : gather (each block covers its batch slice; all SMs gather)
// The two warp groups share NO barriers (GEMM uses bar.sync 0,256).
// ---------------------------------------------------------------------------
__global__ void __launch_bounds__(384, 1)
k1_fused(const float* __restrict__ tokens,
         const int*   __restrict__ mask,
         const float* __restrict__ cls,
         const float* __restrict__ W) {
    __shared__ uint32_t As[NSTAGE * A_WORDS];
    __shared__ uint32_t Bs[NSTAGE * B_WORDS];

    const int tid = threadIdx.x;
    const int bid = blockIdx.x;

    if (tid >= 256) {
        // ---------------- gather warps (4 per block, every block) ----------
        const int gw   = (tid - 256) >> 5;   // 0..3
        const int lane = tid & 31;
        const int wbase = gw * 192;          // j-range start for this warp

        const int b_start = (bid * 16) / 9;        // = bid*256/144
        const int b_end   = ((bid + 1) * 16) / 9;

        for (int b = b_start; b < b_end; b++) {
            // warp ballot scan for first zero (leading-ones length)
            int len = SEQ;
#pragma unroll
            for (int s = 0; s < SEQ / 32; s++) {
                const unsigned z = __ballot_sync(0xffffffffu,
                                                 mask[b * SEQ + s * 32 + lane] == 0);
                if (z) { len = s * 32 + (__ffs(z) - 1); break; }
            }
            const float lenf = (float)len;
            const size_t rowb = (size_t)b * SEQ * H;

#pragma unroll
            for (int it = 0; it < 6; it++) {
                const int j = wbase + it * 32 + lane;
                const int i = b * H + j;
                const uint32_t bits = threefry_bits_partitionable((uint32_t)i);
                const float u = __uint_as_float((bits >> 9) | 0x3f800000u) - 1.0f;
                int idx = (int)floorf(u * lenf);
                if (idx > len - 1) idx = len - 1;
                g_emb[i] = __ldcg(&tokens[rowb + (size_t)idx * H + j]);
            }
        }
        return;
    }

    // ---------------- GEMM warps (groups 0/1) ----------------
    if (bid >= 96) return;
    const int g    = bid / 48;                 // 0 or 1
    const int tile = bid - g * 48;
    const int m0   = (tile / 12) * 64;
    const int n0   = (tile % 12) * 64;

    const float* Wg = W + (g == 0 ? 0 : (size_t)H * H);
    float* Cp = g_S + (size_t)g * BS * H;

    gemm_tile<true>(cls, Wg, Cp, m0, n0, 0, H / BK, As, Bs, tid);
}

// ---------------------------------------------------------------------------
// Kernel 2: emb GEMM (group 2), K-split into 2 deterministic halves.
// Grid (12 n-tiles, 4 m-tiles x 2 splits) = 96 blocks x 256 threads.
// ---------------------------------------------------------------------------
__global__ void __launch_bounds__(256, 1)
k2_embgemm(const float* __restrict__ W) {
    __shared__ uint32_t As[NSTAGE * A_WORDS];
    __shared__ uint32_t Bs[NSTAGE * B_WORDS];

    const int tid   = threadIdx.x;
    const int split = blockIdx.y >> 2;          // 0 or 1
    const int m0    = (blockIdx.y & 3) * 64;
    const int n0    = blockIdx.x * 64;
    const int kb    = split * (H / 2);          // 0 or 384

    const float* Wg = W + (size_t)H * H;        // Wbot
    gemm_tile<false>(g_emb, Wg, g_S2[split], m0, n0, kb, (H / 2) / BK, As, Bs, tid);
}

// ---------------------------------------------------------------------------
// Kernel 3: fused epilogue. One block per batch, 768 threads.
// S2 = S2a + S2b;  e0 = v.tanh(S0+S1+b);  e1 = v.tanh(S0+S2+b); softmax; mix.
// ---------------------------------------------------------------------------
__global__ void __launch_bounds__(768, 2)
epilogue_kernel(const float* __restrict__ cls,
                const float* __restrict__ bias,
                const float* __restrict__ v,
                float*       __restrict__ out) {
    const int b   = blockIdx.x;
    const int tid = threadIdx.x;

    const size_t base = (size_t)b * H + tid;

    const float cv  = cls[base];
    const float ev  = g_emb[base];
    const float s0  = g_S[base];
    const float s1  = g_S[(size_t)BS * H + base];
    const float s2a = g_S2[0][base];
    const float s2b = g_S2[1][base];
    const float bi  = bias[tid];
    const float vv  = v[tid];

    float p0 = fast_tanh(s0 + s1 + bi) * vv;
    float p1 = fast_tanh(s0 + s2a + s2b + bi) * vv;

#pragma unroll
    for (int off = 16; off > 0; off >>= 1) {
        p0 += __shfl_down_sync(0xffffffffu, p0, off);
        p1 += __shfl_down_sync(0xffffffffu, p1, off);
    }
    __shared__ float r0[24], r1[24];
    __shared__ float s_alpha;
    const int w = tid >> 5, l = tid & 31;
    if (l == 0) { r0[w] = p0; r1[w] = p1; }
    __syncthreads();
    if (tid == 0) {
        float e0 = 0.0f, e1 = 0.0f;
#pragma unroll
        for (int i = 0; i < 24; i++) { e0 += r0[i]; e1 += r1[i]; }
        const float m  = fmaxf(e0, e1);
        const float w0 = __expf(e0 - m);
        const float w1 = __expf(e1 - m);
        s_alpha = w0 / (w0 + w1);
    }
    __syncthreads();
    const float a0 = s_alpha;
    out[base] = a0 * cv + (1.0f - a0) * ev;
}

// ---------------------------------------------------------------------------
// kernel_launch — inputs identified BY ELEMENT COUNT
// ---------------------------------------------------------------------------
extern "C" void kernel_launch(void* const* d_in, const int* in_sizes, int n_in,
                              void* d_out, int out_size) {
    const float* tokens = nullptr;
    const float* cls    = nullptr;
    const int*   mask   = nullptr;
    const float* W      = nullptr;
    const float* bias   = nullptr;
    const float* v      = nullptr;

    for (int i = 0; i < n_in; i++) {
        const int sz = in_sizes[i];
        if      (sz == BS * SEQ * H) tokens = (const float*)d_in[i];
        else if (sz == BS * H)       cls    = (const float*)d_in[i];
        else if (sz == BS * SEQ)     mask   = (const int*)  d_in[i];
        else if (sz == 2 * H * H)    W      = (const float*)d_in[i];
        else if (sz == H) {
            if (bias == nullptr)     bias   = (const float*)d_in[i];
            else                     v      = (const float*)d_in[i];
        }
    }
    float* out = (float*)d_out;

    k1_fused<<<144, 384>>>(tokens, mask, cls, W);
    k2_embgemm<<<dim3(12, 8), 256>>>(W);
    epilogue_kernel<<<BS, 768>>>(cls, bias, v, out);
}

// round 14
// speedup vs baseline: 1.2857x; 1.2857x over previous
#include <cuda_runtime.h>
#include <cstdint>

#define BS   256
#define SEQ  512
#define H    768

// Scratch (no allocations allowed)
__device__ float g_emb[BS * H];             // gathered "embraced" rows
__device__ float g_Sa[3][BS * H];           // K-half 0 partial products
__device__ float g_Sb[3][BS * H];           // K-half 1 partial products

// ---------------------------------------------------------------------------
// Threefry-2x32, 20 rounds, key = (0, 42), partitionable scheme:
//   bits32(i) = x0 ^ x1 of threefry2x32(key, (0, i))
// ---------------------------------------------------------------------------
__device__ __forceinline__ uint32_t rotl32(uint32_t x, int r) {
    return (x << r) | (x >> (32 - r));
}

__device__ __forceinline__ uint32_t threefry_bits_partitionable(uint32_t i) {
    const uint32_t k0 = 0u, k1 = 42u;
    const uint32_t ks2 = 0x1BD11BDAu ^ k0 ^ k1;
    uint32_t x0 = 0u + k0;
    uint32_t x1 = i  + k1;

#define TF_BLOCK(r0_, r1_, r2_, r3_)                                   \
    x0 += x1; x1 = rotl32(x1, r0_); x1 ^= x0;                          \
    x0 += x1; x1 = rotl32(x1, r1_); x1 ^= x0;                          \
    x0 += x1; x1 = rotl32(x1, r2_); x1 ^= x0;                          \
    x0 += x1; x1 = rotl32(x1, r3_); x1 ^= x0;

    TF_BLOCK(13, 15, 26, 6)   x0 += k1;  x1 += ks2 + 1u;
    TF_BLOCK(17, 29, 16, 24)  x0 += ks2; x1 += k0  + 2u;
    TF_BLOCK(13, 15, 26, 6)   x0 += k0;  x1 += k1  + 3u;
    TF_BLOCK(17, 29, 16, 24)  x0 += k1;  x1 += ks2 + 4u;
    TF_BLOCK(13, 15, 26, 6)   x0 += ks2; x1 += k0  + 5u;
#undef TF_BLOCK
    return x0 ^ x1;
}

// fast tanh via MUFU.EX2: exact limits at +-inf
__device__ __forceinline__ float fast_tanh(float x) {
    return 1.0f - 2.0f / (__expf(2.0f * x) + 1.0f);
}

// ---------------------------------------------------------------------------
// Kernel 1: fused length-scan + gather. One block per batch, 384 threads,
// 2 elements per thread, L2-only gather loads. (Hard serial segment at the
// random-access DRAM ceiling — keep exclusive on the chip.)
// ---------------------------------------------------------------------------
__global__ void __launch_bounds__(384, 4)
prep_kernel(const float* __restrict__ tokens,
            const int*   __restrict__ mask) {
    const int b   = blockIdx.x;
    const int tid = threadIdx.x;   // 0..383

    __shared__ int s_len;
    if (tid == 0) s_len = SEQ;
    __syncthreads();
    if (mask[b * SEQ + tid] == 0) atomicMin(&s_len, tid);
    {
        const int t2 = tid + 384;
        if (t2 < SEQ && mask[b * SEQ + t2] == 0) atomicMin(&s_len, t2);
    }
    __syncthreads();
    const int   len  = s_len;
    const float lenf = (float)len;

    const int j0 = tid * 2;
    const int i0 = b * H + j0;

    const uint32_t bits0 = threefry_bits_partitionable((uint32_t)i0);
    const uint32_t bits1 = threefry_bits_partitionable((uint32_t)(i0 + 1));
    const float u0 = __uint_as_float((bits0 >> 9) | 0x3f800000u) - 1.0f;
    const float u1 = __uint_as_float((bits1 >> 9) | 0x3f800000u) - 1.0f;
    int idx0 = (int)floorf(u0 * lenf);
    int idx1 = (int)floorf(u1 * lenf);
    if (idx0 > len - 1) idx0 = len - 1;
    if (idx1 > len - 1) idx1 = len - 1;

    const size_t rowb = (size_t)b * SEQ * H;
    const float e0 = __ldcg(&tokens[rowb + (size_t)idx0 * H + j0]);
    const float e1 = __ldcg(&tokens[rowb + (size_t)idx1 * H + j0 + 1]);
    *reinterpret_cast<float2*>(&g_emb[i0]) = make_float2(e0, e1);
}

// ---------------------------------------------------------------------------
// Kernel 2: TF32 GEMM, R8 config (BM=64, BN=64, BK=16, 4-stage cp.async)
// with K-SPLIT 2: each block computes a 64x64 tile over half the K range.
// Grid (12, 24) = 288 blocks (2/SM) — stalls interleave across co-resident
// blocks; total staging traffic unchanged vs unsplit.
// y = g*8 + mtile*2 + split.
// ---------------------------------------------------------------------------
#define BK     16
#define NITH   ((H / 2) / BK)   // 24 iterations per half
#define NSTAGE 4
#define APAD   20
#define BPAD   72
#define A_WORDS (64 * APAD)   // 1280
#define B_WORDS (BK * BPAD)   // 1152

__device__ __forceinline__ void cp16(uint32_t saddr, const void* gaddr) {
    asm volatile("cp.async.ca.shared.global [%0], [%1], 16;\n"
                 :: "r"(saddr), "l"(gaddr));
}
__device__ __forceinline__ void cp_commit() {
    asm volatile("cp.async.commit_group;\n");
}
template <int N>
__device__ __forceinline__ void cp_wait() {
    asm volatile("cp.async.wait_group %0;\n" :: "n"(N));
}

__device__ __forceinline__ void mma_tf32(float* d, const uint32_t* a, const uint32_t* b) {
    asm volatile(
        "mma.sync.aligned.m16n8k8.row.col.f32.tf32.tf32.f32 "
        "{%0,%1,%2,%3}, {%4,%5,%6,%7}, {%8,%9}, {%0,%1,%2,%3};\n"
        : "+f"(d[0]), "+f"(d[1]), "+f"(d[2]), "+f"(d[3])
        : "r"(a[0]), "r"(a[1]), "r"(a[2]), "r"(a[3]), "r"(b[0]), "r"(b[1]));
}

__global__ void __launch_bounds__(256, 2)
gemm_tf32_kernel(const float* __restrict__ cls,
                 const float* __restrict__ W) {
    const int g     = blockIdx.y >> 3;          // group 0..2
    const int m0    = ((blockIdx.y >> 1) & 3) * 64;
    const int split = blockIdx.y & 1;
    const int n0    = blockIdx.x * 64;
    const int kb    = split * (H / 2);          // 0 or 384

    const float* __restrict__ A  = (g == 2) ? g_emb : cls;
    const float* __restrict__ Wg = W + (g == 0 ? 0 : (size_t)H * H);

    __shared__ uint32_t As[NSTAGE][A_WORDS];
    __shared__ uint32_t Bs[NSTAGE][B_WORDS];

    const int tid  = threadIdx.x;
    const int warp = tid >> 5;
    const int lane = tid & 31;
    const int wm   = (warp & 1) * 32;
    const int wn   = (warp >> 1) * 16;
    const int grp  = lane >> 2;
    const int tig  = lane & 3;

    const int a_r = tid >> 2;
    const int a_c = (tid & 3) * 4;
    const int b_r = tid >> 4;
    const int b_c = (tid & 15) * 4;

    const float* a_src = &A[(m0 + a_r) * H + kb + a_c];
    const float* b_src = &Wg[(size_t)(kb + b_r) * H + n0 + b_c];

    const uint32_t s_as = (uint32_t)__cvta_generic_to_shared(&As[0][0]) +
                          (uint32_t)((a_r * APAD + a_c) * 4);
    const uint32_t s_bs = (uint32_t)__cvta_generic_to_shared(&Bs[0][0]) +
                          (uint32_t)((b_r * BPAD + b_c) * 4);

    float acc[2][2][4];
#pragma unroll
    for (int mi = 0; mi < 2; mi++)
#pragma unroll
        for (int ni = 0; ni < 2; ni++)
#pragma unroll
            for (int r = 0; r < 4; r++) acc[mi][ni][r] = 0.0f;

#pragma unroll
    for (int s = 0; s < NSTAGE - 1; s++) {
        cp16(s_as + (uint32_t)(s * A_WORDS * 4), a_src + s * BK);
        cp16(s_bs + (uint32_t)(s * B_WORDS * 4), b_src + (size_t)(s * BK) * H);
        cp_commit();
    }

    for (int it = 0; it < NITH; it++) {
        cp_wait<NSTAGE - 2>();
        __syncthreads();

        const int nx = it + NSTAGE - 1;
        if (nx < NITH) {
            const int buf = nx & (NSTAGE - 1);
            cp16(s_as + (uint32_t)(buf * A_WORDS * 4), a_src + nx * BK);
            cp16(s_bs + (uint32_t)(buf * B_WORDS * 4), b_src + (size_t)(nx * BK) * H);
        }
        cp_commit();

        const uint32_t* Asb = As[it & (NSTAGE - 1)];
        const uint32_t* Bsb = Bs[it & (NSTAGE - 1)];
#pragma unroll
        for (int ks = 0; ks < BK; ks += 8) {
            uint32_t afr[2][4];
#pragma unroll
            for (int mi = 0; mi < 2; mi++) {
                const int rbase = (wm + mi * 16 + grp) * APAD + ks + tig;
                afr[mi][0] = Asb[rbase];
                afr[mi][1] = Asb[rbase + 8 * APAD];
                afr[mi][2] = Asb[rbase + 4];
                afr[mi][3] = Asb[rbase + 8 * APAD + 4];
            }
            uint32_t bfr[2][2];
#pragma unroll
            for (int ni = 0; ni < 2; ni++) {
                const int cbase = (ks + tig) * BPAD + wn + ni * 8 + grp;
                bfr[ni][0] = Bsb[cbase];
                bfr[ni][1] = Bsb[cbase + 4 * BPAD];
            }
#pragma unroll
            for (int mi = 0; mi < 2; mi++)
#pragma unroll
                for (int ni = 0; ni < 2; ni++)
                    mma_tf32(acc[mi][ni], afr[mi], bfr[ni]);
        }
    }

    float* __restrict__ Cp = (split == 0 ? g_Sa[g] : g_Sb[g]);
#pragma unroll
    for (int mi = 0; mi < 2; mi++) {
#pragma unroll
        for (int ni = 0; ni < 2; ni++) {
            const int col = n0 + wn + ni * 8 + tig * 2;
            const int r0  = m0 + wm + mi * 16 + grp;
            *reinterpret_cast<float2*>(&Cp[(size_t)r0 * H + col]) =
                make_float2(acc[mi][ni][0], acc[mi][ni][1]);
            *reinterpret_cast<float2*>(&Cp[(size_t)(r0 + 8) * H + col]) =
                make_float2(acc[mi][ni][2], acc[mi][ni][3]);
        }
    }
}

// ---------------------------------------------------------------------------
// Kernel 3: fused epilogue. One block per batch, 768 threads.
// S_g = Sa[g] + Sb[g] (fixed order); e_k = v.tanh(S0+S_k+b); softmax; mix.
// ---------------------------------------------------------------------------
__global__ void __launch_bounds__(768, 2)
epilogue_kernel(const float* __restrict__ cls,
                const float* __restrict__ bias,
                const float* __restrict__ v,
                float*       __restrict__ out) {
    const int b   = blockIdx.x;
    const int tid = threadIdx.x;

    const size_t base = (size_t)b * H + tid;

    const float cv = cls[base];
    const float ev = g_emb[base];
    const float s0 = g_Sa[0][base] + g_Sb[0][base];
    const float s1 = g_Sa[1][base] + g_Sb[1][base];
    const float s2 = g_Sa[2][base] + g_Sb[2][base];
    const float bi = bias[tid];
    const float vv = v[tid];

    float p0 = fast_tanh(s0 + s1 + bi) * vv;
    float p1 = fast_tanh(s0 + s2 + bi) * vv;

#pragma unroll
    for (int off = 16; off > 0; off >>= 1) {
        p0 += __shfl_down_sync(0xffffffffu, p0, off);
        p1 += __shfl_down_sync(0xffffffffu, p1, off);
    }
    __shared__ float r0[24], r1[24];
    __shared__ float s_alpha;
    const int w = tid >> 5, l = tid & 31;
    if (l == 0) { r0[w] = p0; r1[w] = p1; }
    __syncthreads();
    if (tid == 0) {
        float e0 = 0.0f, e1 = 0.0f;
#pragma unroll
        for (int i = 0; i < 24; i++) { e0 += r0[i]; e1 += r1[i]; }
        const float m  = fmaxf(e0, e1);
        const float w0 = __expf(e0 - m);
        const float w1 = __expf(e1 - m);
        s_alpha = w0 / (w0 + w1);
    }
    __syncthreads();
    const float a0 = s_alpha;
    out[base] = a0 * cv + (1.0f - a0) * ev;
}

// ---------------------------------------------------------------------------
// kernel_launch — inputs identified BY ELEMENT COUNT
// ---------------------------------------------------------------------------
extern "C" void kernel_launch(void* const* d_in, const int* in_sizes, int n_in,
                              void* d_out, int out_size) {
    const float* tokens = nullptr;
    const float* cls    = nullptr;
    const int*   mask   = nullptr;
    const float* W      = nullptr;
    const float* bias   = nullptr;
    const float* v      = nullptr;

    for (int i = 0; i < n_in; i++) {
        const int sz = in_sizes[i];
        if      (sz == BS * SEQ * H) tokens = (const float*)d_in[i];
        else if (sz == BS * H)       cls    = (const float*)d_in[i];
        else if (sz == BS * SEQ)     mask   = (const int*)  d_in[i];
        else if (sz == 2 * H * H)    W      = (const float*)d_in[i];
        else if (sz == H) {
            if (bias == nullptr)     bias   = (const float*)d_in[i];
            else                     v      = (const float*)d_in[i];
        }
    }
    float* out = (float*)d_out;

    prep_kernel<<<BS, 384>>>(tokens, mask);
    gemm_tf32_kernel<<<dim3(12, 24), 256>>>(cls, W);
    epilogue_kernel<<<BS, 768>>>(cls, bias, v, out);
}

// round 15
// speedup vs baseline: 1.3053x; 1.0153x over previous
#include <cuda_runtime.h>
#include <cstdint>

#define BS   256
#define SEQ  512
#define H    768

// Scratch (no allocations allowed)
__device__ float g_emb[BS * H];               // gathered "embraced" rows
__device__ float g_Sp[4][3][BS * H];          // [ksplit][group] partial products

// ---------------------------------------------------------------------------
// Threefry-2x32, 20 rounds, key = (0, 42), partitionable scheme:
//   bits32(i) = x0 ^ x1 of threefry2x32(key, (0, i))
// ---------------------------------------------------------------------------
__device__ __forceinline__ uint32_t rotl32(uint32_t x, int r) {
    return (x << r) | (x >> (32 - r));
}

__device__ __forceinline__ uint32_t threefry_bits_partitionable(uint32_t i) {
    const uint32_t k0 = 0u, k1 = 42u;
    const uint32_t ks2 = 0x1BD11BDAu ^ k0 ^ k1;
    uint32_t x0 = 0u + k0;
    uint32_t x1 = i  + k1;

#define TF_BLOCK(r0_, r1_, r2_, r3_)                                   \
    x0 += x1; x1 = rotl32(x1, r0_); x1 ^= x0;                          \
    x0 += x1; x1 = rotl32(x1, r1_); x1 ^= x0;                          \
    x0 += x1; x1 = rotl32(x1, r2_); x1 ^= x0;                          \
    x0 += x1; x1 = rotl32(x1, r3_); x1 ^= x0;

    TF_BLOCK(13, 15, 26, 6)   x0 += k1;  x1 += ks2 + 1u;
    TF_BLOCK(17, 29, 16, 24)  x0 += ks2; x1 += k0  + 2u;
    TF_BLOCK(13, 15, 26, 6)   x0 += k0;  x1 += k1  + 3u;
    TF_BLOCK(17, 29, 16, 24)  x0 += k1;  x1 += ks2 + 4u;
    TF_BLOCK(13, 15, 26, 6)   x0 += ks2; x1 += k0  + 5u;
#undef TF_BLOCK
    return x0 ^ x1;
}

// fast tanh via MUFU.EX2: exact limits at +-inf
__device__ __forceinline__ float fast_tanh(float x) {
    return 1.0f - 2.0f / (__expf(2.0f * x) + 1.0f);
}

// ---------------------------------------------------------------------------
// Kernel 1: fused length-scan + gather. One block per batch, 384 threads.
// Hard serial segment at the random-access DRAM ceiling; keep chip-exclusive.
// ---------------------------------------------------------------------------
__global__ void __launch_bounds__(384, 4)
prep_kernel(const float* __restrict__ tokens,
            const int*   __restrict__ mask) {
    const int b   = blockIdx.x;
    const int tid = threadIdx.x;   // 0..383

    __shared__ int s_len;
    if (tid == 0) s_len = SEQ;
    __syncthreads();
    if (mask[b * SEQ + tid] == 0) atomicMin(&s_len, tid);
    {
        const int t2 = tid + 384;
        if (t2 < SEQ && mask[b * SEQ + t2] == 0) atomicMin(&s_len, t2);
    }
    __syncthreads();
    const int   len  = s_len;
    const float lenf = (float)len;

    const int j0 = tid * 2;
    const int i0 = b * H + j0;

    const uint32_t bits0 = threefry_bits_partitionable((uint32_t)i0);
    const uint32_t bits1 = threefry_bits_partitionable((uint32_t)(i0 + 1));
    const float u0 = __uint_as_float((bits0 >> 9) | 0x3f800000u) - 1.0f;
    const float u1 = __uint_as_float((bits1 >> 9) | 0x3f800000u) - 1.0f;
    int idx0 = (int)floorf(u0 * lenf);
    int idx1 = (int)floorf(u1 * lenf);
    if (idx0 > len - 1) idx0 = len - 1;
    if (idx1 > len - 1) idx1 = len - 1;

    const size_t rowb = (size_t)b * SEQ * H;
    const float e0 = __ldcg(&tokens[rowb + (size_t)idx0 * H + j0]);
    const float e1 = __ldcg(&tokens[rowb + (size_t)idx1 * H + j0 + 1]);
    *reinterpret_cast<float2*>(&g_emb[i0]) = make_float2(e0, e1);
}

// ---------------------------------------------------------------------------
// Kernel 2: TF32 GEMM v2 — LDS-bandwidth optimized.
// BM=128, BN=128, warp grid 2m x 4n, warp tile 64x32 (0.1875 B/MAC from smem,
// 2x better than 32x16). BK=16, 4-stage cp.async, K-SPLIT 4 -> 144 blocks.
// y = g*8 + mtile*4 + split.  Dynamic smem (75.8KB).
// ---------------------------------------------------------------------------
#define BK     16
#define NITQ   ((H / 4) / BK)   // 12 iterations per quarter
#define NSTAGE 4
#define APAD   20
#define BPAD   136
#define A_WORDS (128 * APAD)   // 2560
#define B_WORDS (BK * BPAD)    // 2176
#define GEMM_SMEM (NSTAGE * (A_WORDS + B_WORDS) * 4)   // 75776 bytes

__device__ __forceinline__ void cp16(uint32_t saddr, const void* gaddr) {
    asm volatile("cp.async.ca.shared.global [%0], [%1], 16;\n"
                 :: "r"(saddr), "l"(gaddr));
}
__device__ __forceinline__ void cp_commit() {
    asm volatile("cp.async.commit_group;\n");
}
template <int N>
__device__ __forceinline__ void cp_wait() {
    asm volatile("cp.async.wait_group %0;\n" :: "n"(N));
}

__device__ __forceinline__ void mma_tf32(float* d, const uint32_t* a, const uint32_t* b) {
    asm volatile(
        "mma.sync.aligned.m16n8k8.row.col.f32.tf32.tf32.f32 "
        "{%0,%1,%2,%3}, {%4,%5,%6,%7}, {%8,%9}, {%0,%1,%2,%3};\n"
        : "+f"(d[0]), "+f"(d[1]), "+f"(d[2]), "+f"(d[3])
        : "r"(a[0]), "r"(a[1]), "r"(a[2]), "r"(a[3]), "r"(b[0]), "r"(b[1]));
}

__global__ void __launch_bounds__(256, 1)
gemm_tf32_kernel(const float* __restrict__ cls,
                 const float* __restrict__ W) {
    extern __shared__ uint32_t sm[];
    uint32_t* As = sm;                          // NSTAGE * A_WORDS
    uint32_t* Bs = sm + NSTAGE * A_WORDS;       // NSTAGE * B_WORDS

    const int g     = blockIdx.y >> 3;          // group 0..2
    const int m0    = ((blockIdx.y >> 2) & 1) * 128;
    const int split = blockIdx.y & 3;
    const int n0    = blockIdx.x * 128;
    const int kb    = split * (H / 4);          // 0, 192, 384, 576

    const float* __restrict__ A  = (g == 2) ? g_emb : cls;
    const float* __restrict__ Wg = W + (g == 0 ? 0 : (size_t)H * H);

    const int tid  = threadIdx.x;
    const int warp = tid >> 5;
    const int lane = tid & 31;
    const int wm   = (warp & 1) * 64;    // 2 m warps x 64 rows
    const int wn   = (warp >> 1) * 32;   // 4 n warps x 32 cols
    const int grp  = lane >> 2;
    const int tig  = lane & 3;

    // staging: A 128x16 floats -> 8/thread (2 cp16); B 16x128 -> 8/thread
    const int a_r = tid >> 1;            // 0..127
    const int a_c = (tid & 1) * 8;       // 0 or 8
    const int b_r = tid >> 4;            // 0..15
    const int b_c = (tid & 15) * 8;      // 0..120

    const float* a_src = &A[(m0 + a_r) * H + kb + a_c];
    const float* b_src = &Wg[(size_t)(kb + b_r) * H + n0 + b_c];

    const uint32_t s_as = (uint32_t)__cvta_generic_to_shared(As) +
                          (uint32_t)((a_r * APAD + a_c) * 4);
    const uint32_t s_bs = (uint32_t)__cvta_generic_to_shared(Bs) +
                          (uint32_t)((b_r * BPAD + b_c) * 4);

    float acc[4][4][4];
#pragma unroll
    for (int mi = 0; mi < 4; mi++)
#pragma unroll
        for (int ni = 0; ni < 4; ni++)
#pragma unroll
            for (int r = 0; r < 4; r++) acc[mi][ni][r] = 0.0f;

#pragma unroll
    for (int s = 0; s < NSTAGE - 1; s++) {
        cp16(s_as + (uint32_t)(s * A_WORDS * 4),      a_src + s * BK);
        cp16(s_as + (uint32_t)(s * A_WORDS * 4) + 16, a_src + s * BK + 4);
        cp16(s_bs + (uint32_t)(s * B_WORDS * 4),      b_src + (size_t)(s * BK) * H);
        cp16(s_bs + (uint32_t)(s * B_WORDS * 4) + 16, b_src + (size_t)(s * BK) * H + 4);
        cp_commit();
    }

    for (int it = 0; it < NITQ; it++) {
        cp_wait<NSTAGE - 2>();
        __syncthreads();

        const int nx = it + NSTAGE - 1;
        if (nx < NITQ) {
            const int buf = nx & (NSTAGE - 1);
            cp16(s_as + (uint32_t)(buf * A_WORDS * 4),      a_src + nx * BK);
            cp16(s_as + (uint32_t)(buf * A_WORDS * 4) + 16, a_src + nx * BK + 4);
            cp16(s_bs + (uint32_t)(buf * B_WORDS * 4),      b_src + (size_t)(nx * BK) * H);
            cp16(s_bs + (uint32_t)(buf * B_WORDS * 4) + 16, b_src + (size_t)(nx * BK) * H + 4);
        }
        cp_commit();

        const uint32_t* Asb = As + (it & (NSTAGE - 1)) * A_WORDS;
        const uint32_t* Bsb = Bs + (it & (NSTAGE - 1)) * B_WORDS;
#pragma unroll
        for (int ks = 0; ks < BK; ks += 8) {
            uint32_t afr[4][4];
#pragma unroll
            for (int mi = 0; mi < 4; mi++) {
                const int rbase = (wm + mi * 16 + grp) * APAD + ks + tig;
                afr[mi][0] = Asb[rbase];
                afr[mi][1] = Asb[rbase + 8 * APAD];
                afr[mi][2] = Asb[rbase + 4];
                afr[mi][3] = Asb[rbase + 8 * APAD + 4];
            }
            uint32_t bfr[4][2];
#pragma unroll
            for (int ni = 0; ni < 4; ni++) {
                const int cbase = (ks + tig) * BPAD + wn + ni * 8 + grp;
                bfr[ni][0] = Bsb[cbase];
                bfr[ni][1] = Bsb[cbase + 4 * BPAD];
            }
#pragma unroll
            for (int mi = 0; mi < 4; mi++)
#pragma unroll
                for (int ni = 0; ni < 4; ni++)
                    mma_tf32(acc[mi][ni], afr[mi], bfr[ni]);
        }
    }

    float* __restrict__ Cp = g_Sp[split][g];
#pragma unroll
    for (int mi = 0; mi < 4; mi++) {
#pragma unroll
        for (int ni = 0; ni < 4; ni++) {
            const int col = n0 + wn + ni * 8 + tig * 2;
            const int r0  = m0 + wm + mi * 16 + grp;
            *reinterpret_cast<float2*>(&Cp[(size_t)r0 * H + col]) =
                make_float2(acc[mi][ni][0], acc[mi][ni][1]);
            *reinterpret_cast<float2*>(&Cp[(size_t)(r0 + 8) * H + col]) =
                make_float2(acc[mi][ni][2], acc[mi][ni][3]);
        }
    }
}

// ---------------------------------------------------------------------------
// Kernel 3: fused epilogue. One block per batch, 768 threads.
// S_g = sum of 4 K-split partials (fixed order); e_k = v.tanh(S0+S_k+b);
// softmax; out = a0*cls + a1*emb.
// ---------------------------------------------------------------------------
__global__ void __launch_bounds__(768, 2)
epilogue_kernel(const float* __restrict__ cls,
                const float* __restrict__ bias,
                const float* __restrict__ v,
                float*       __restrict__ out) {
    const int b   = blockIdx.x;
    const int tid = threadIdx.x;

    const size_t base = (size_t)b * H + tid;

    const float cv = cls[base];
    const float ev = g_emb[base];
    float s0 = 0.f, s1 = 0.f, s2 = 0.f;
#pragma unroll
    for (int s = 0; s < 4; s++) {
        s0 += g_Sp[s][0][base];
        s1 += g_Sp[s][1][base];
        s2 += g_Sp[s][2][base];
    }
    const float bi = bias[tid];
    const float vv = v[tid];

    float p0 = fast_tanh(s0 + s1 + bi) * vv;
    float p1 = fast_tanh(s0 + s2 + bi) * vv;

#pragma unroll
    for (int off = 16; off > 0; off >>= 1) {
        p0 += __shfl_down_sync(0xffffffffu, p0, off);
        p1 += __shfl_down_sync(0xffffffffu, p1, off);
    }
    __shared__ float r0[24], r1[24];
    __shared__ float s_alpha;
    const int w = tid >> 5, l = tid & 31;
    if (l == 0) { r0[w] = p0; r1[w] = p1; }
    __syncthreads();
    if (tid == 0) {
        float e0 = 0.0f, e1 = 0.0f;
#pragma unroll
        for (int i = 0; i < 24; i++) { e0 += r0[i]; e1 += r1[i]; }
        const float m  = fmaxf(e0, e1);
        const float w0 = __expf(e0 - m);
        const float w1 = __expf(e1 - m);
        s_alpha = w0 / (w0 + w1);
    }
    __syncthreads();
    const float a0 = s_alpha;
    out[base] = a0 * cv + (1.0f - a0) * ev;
}

// ---------------------------------------------------------------------------
// kernel_launch — inputs identified BY ELEMENT COUNT
// ---------------------------------------------------------------------------
extern "C" void kernel_launch(void* const* d_in, const int* in_sizes, int n_in,
                              void* d_out, int out_size) {
    const float* tokens = nullptr;
    const float* cls    = nullptr;
    const int*   mask   = nullptr;
    const float* W      = nullptr;
    const float* bias   = nullptr;
    const float* v      = nullptr;

    for (int i = 0; i < n_in; i++) {
        const int sz = in_sizes[i];
        if      (sz == BS * SEQ * H) tokens = (const float*)d_in[i];
        else if (sz == BS * H)       cls    = (const float*)d_in[i];
        else if (sz == BS * SEQ)     mask   = (const int*)  d_in[i];
        else if (sz == 2 * H * H)    W      = (const float*)d_in[i];
        else if (sz == H) {
            if (bias == nullptr)     bias   = (const float*)d_in[i];
            else                     v      = (const float*)d_in[i];
        }
    }
    float* out = (float*)d_out;

    // idempotent; capture-safe (not a stream op)
    cudaFuncSetAttribute(gemm_tf32_kernel,
                         cudaFuncAttributeMaxDynamicSharedMemorySize, GEMM_SMEM);

    prep_kernel<<<BS, 384>>>(tokens, mask);
    gemm_tf32_kernel<<<dim3(6, 24), 256, GEMM_SMEM>>>(cls, W);
    epilogue_kernel<<<BS, 768>>>(cls, bias, v, out);
}